// round 9
// baseline (speedup 1.0000x reference)
#include <cuda_runtime.h>
#include <cstdint>

#define KC  256      // CLUST_SIZE
#define TPB 128      // threads per CTA; each thread owns rows 2t and 2t+1

typedef unsigned long long u64;

// ---- packed f32x2 ops (Blackwell). Lane rounding == scalar .rn rounding,
// ---- so results are bitwise identical to the scalar reference chain. ----
__device__ __forceinline__ u64 mul2(u64 a, u64 b) {
    u64 r; asm("mul.rn.f32x2 %0, %1, %2;" : "=l"(r) : "l"(a), "l"(b)); return r;
}
__device__ __forceinline__ u64 add2(u64 a, u64 b) {
    u64 r; asm("add.rn.f32x2 %0, %1, %2;" : "=l"(r) : "l"(a), "l"(b)); return r;
}
__device__ __forceinline__ u64 fma2p(u64 a, u64 b, u64 c) {
    u64 r; asm("fma.rn.f32x2 %0, %1, %2, %3;" : "=l"(r) : "l"(a), "l"(b), "l"(c)); return r;
}
__device__ __forceinline__ u64 pk2(float lo, float hi) {
    union { float2 f; u64 u; } c; c.f = make_float2(lo, hi); return c.u;
}
__device__ __forceinline__ float2 f2(u64 v) {
    union { u64 u; float2 f; } c; c.u = v; return c.f;
}

// min-blocks-per-SM 10 => <=51 regs => 40 warps/SM theoretical (62.5%).
__global__ __launch_bounds__(TPB, 10)
void clust_geo_edge_kernel(const float* __restrict__ data,     // [N_VOX, 5]
                           const int*   __restrict__ clusts,   // [N_CLUST, 256]
                           const int*   __restrict__ ei,       // [2, E]
                           float*       __restrict__ out,      // [E, 19]
                           int n_edge)
{
    __shared__ float4 s1[KC];        // cluster-1 rows: {x, y, z, h=0.5*n}
    // cluster-2 j-pairs, byte layout == packed u64 pairs:
    //   sA[p] = {x0,x1,y0,y1} -> ulonglong2 { (x0,x1), (y0,y1) }
    //   sB[p] = {z0,z1,h0,h1} -> ulonglong2 { (z0,z1), (h0,h1) }
    __shared__ float4 sA[KC / 2];
    __shared__ float4 sB[KC / 2];
    __shared__ float  wv[TPB / 32];
    __shared__ int    wi[TPB / 32];

    const int e = blockIdx.x;
    const int t = threadIdx.x;
    const int c1 = ei[e];
    const int c2 = ei[n_edge + e];

    // ---- gather; arithmetic bit-identical to the passing rounds:
    //      n via pair02 tree rn(rn(x^2+z^2)+y^2), h = 0.5*n (exact) ----
    float4 r0, r1;
    {
        int2 va = reinterpret_cast<const int2*>(clusts + c1 * KC)[t];
        const float* pa = data + (size_t)va.x * 5;
        const float* pb = data + (size_t)va.y * 5;
        float x = pa[0], y = pa[1], z = pa[2];
        float h = 0.5f * __fadd_rn(__fadd_rn(__fmul_rn(x, x), __fmul_rn(z, z)),
                                   __fmul_rn(y, y));
        r0 = make_float4(x, y, z, h);
        s1[2 * t] = r0;
        x = pb[0]; y = pb[1]; z = pb[2];
        h = 0.5f * __fadd_rn(__fadd_rn(__fmul_rn(x, x), __fmul_rn(z, z)),
                             __fmul_rn(y, y));
        r1 = make_float4(x, y, z, h);
        s1[2 * t + 1] = r1;

        int2 vb = reinterpret_cast<const int2*>(clusts + c2 * KC)[t];
        const float* qa = data + (size_t)vb.x * 5;
        const float* qb = data + (size_t)vb.y * 5;
        float X0 = qa[0], Y0 = qa[1], Z0 = qa[2];
        float H0 = 0.5f * __fadd_rn(__fadd_rn(__fmul_rn(X0, X0), __fmul_rn(Z0, Z0)),
                                    __fmul_rn(Y0, Y0));
        float X1 = qb[0], Y1 = qb[1], Z1 = qb[2];
        float H1 = 0.5f * __fadd_rn(__fadd_rn(__fmul_rn(X1, X1), __fmul_rn(Z1, Z1)),
                                    __fmul_rn(Y1, Y1));
        sA[t] = make_float4(X0, X1, Y0, Y1);
        sB[t] = make_float4(Z0, Z1, H0, H1);
    }
    __syncthreads();

    // Row constants, negated so the fma chain yields -c exactly
    // ( rn(-x) == -rn(x);  d = (h1+h2) + (-c)  is bitwise  (h1+h2) - c ).
    const u64 nx0 = pk2(-r0.x, -r0.x), ny0 = pk2(-r0.y, -r0.y),
              nz0 = pk2(-r0.z, -r0.z), hh0 = pk2( r0.w,  r0.w);
    const u64 nx1 = pk2(-r1.x, -r1.x), ny1 = pk2(-r1.y, -r1.y),
              nz1 = pk2(-r1.z, -r1.z), hh1 = pk2( r1.w,  r1.w);

    const ulonglong2* qAB = reinterpret_cast<const ulonglong2*>(sA);
    const ulonglong2* qZH = reinterpret_cast<const ulonglong2*>(sB);

    const float INF = __int_as_float(0x7f800000);
    float best0 = INF, best1 = INF;
    int   bj0 = 0,     bj1 = 0;

#pragma unroll 2
    for (int kb = 0; kb < KC / 8; ++kb) {           // 8 j per block = 4 packed pairs
        ulonglong2 ab0 = qAB[kb * 4 + 0], zh0 = qZH[kb * 4 + 0];
        ulonglong2 ab1 = qAB[kb * 4 + 1], zh1 = qZH[kb * 4 + 1];
        ulonglong2 ab2 = qAB[kb * 4 + 2], zh2 = qZH[kb * 4 + 2];
        ulonglong2 ab3 = qAB[kb * 4 + 3], zh3 = qZH[kb * 4 + 3];

        // ---------------- row 0 ----------------
        {
            u64 d0 = add2(add2(hh0, zh0.y), fma2p(nz0, zh0.x, fma2p(ny0, ab0.y, mul2(nx0, ab0.x))));
            u64 d1 = add2(add2(hh0, zh1.y), fma2p(nz0, zh1.x, fma2p(ny0, ab1.y, mul2(nx0, ab1.x))));
            u64 d2 = add2(add2(hh0, zh2.y), fma2p(nz0, zh2.x, fma2p(ny0, ab2.y, mul2(nx0, ab2.x))));
            u64 d3 = add2(add2(hh0, zh3.y), fma2p(nz0, zh3.x, fma2p(ny0, ab3.y, mul2(nx0, ab3.x))));
            float2 a = f2(d0), b = f2(d1), c = f2(d2), d = f2(d3);
            float bm = fminf(fminf(fminf(a.x, a.y), fminf(b.x, b.y)),
                             fminf(fminf(c.x, c.y), fminf(d.x, d.y)));
            if (bm < best0) {                       // strict <: earlier block wins ties
                best0 = bm;
                int jb = kb * 8;                    // descending overwrite -> lowest j wins
                if (d.y == bm) bj0 = jb + 7;
                if (d.x == bm) bj0 = jb + 6;
                if (c.y == bm) bj0 = jb + 5;
                if (c.x == bm) bj0 = jb + 4;
                if (b.y == bm) bj0 = jb + 3;
                if (b.x == bm) bj0 = jb + 2;
                if (a.y == bm) bj0 = jb + 1;
                if (a.x == bm) bj0 = jb + 0;
            }
        }
        // ---------------- row 1 ----------------
        {
            u64 d0 = add2(add2(hh1, zh0.y), fma2p(nz1, zh0.x, fma2p(ny1, ab0.y, mul2(nx1, ab0.x))));
            u64 d1 = add2(add2(hh1, zh1.y), fma2p(nz1, zh1.x, fma2p(ny1, ab1.y, mul2(nx1, ab1.x))));
            u64 d2 = add2(add2(hh1, zh2.y), fma2p(nz1, zh2.x, fma2p(ny1, ab2.y, mul2(nx1, ab2.x))));
            u64 d3 = add2(add2(hh1, zh3.y), fma2p(nz1, zh3.x, fma2p(ny1, ab3.y, mul2(nx1, ab3.x))));
            float2 a = f2(d0), b = f2(d1), c = f2(d2), d = f2(d3);
            float bm = fminf(fminf(fminf(a.x, a.y), fminf(b.x, b.y)),
                             fminf(fminf(c.x, c.y), fminf(d.x, d.y)));
            if (bm < best1) {
                best1 = bm;
                int jb = kb * 8;
                if (d.y == bm) bj1 = jb + 7;
                if (d.x == bm) bj1 = jb + 6;
                if (c.y == bm) bj1 = jb + 5;
                if (c.x == bm) bj1 = jb + 4;
                if (b.y == bm) bj1 = jb + 3;
                if (b.x == bm) bj1 = jb + 2;
                if (a.y == bm) bj1 = jb + 1;
                if (a.x == bm) bj1 = jb + 0;
            }
        }
    }

    // Merge the two rows. Row 2t's flat indices are all smaller than row
    // 2t+1's, so strict < keeps first-occurrence semantics exactly.
    float bv;  int bf;
    if (best1 < best0) { bv = best1; bf = ((2 * t + 1) << 8) | bj1; }
    else               { bv = best0; bf = ((2 * t)     << 8) | bj0; }

    // Warp shuffle reduction, lexicographic (value, flat index) — no barriers.
#pragma unroll
    for (int off = 16; off > 0; off >>= 1) {
        float ov = __shfl_down_sync(0xffffffffu, bv, off);
        int   oi = __shfl_down_sync(0xffffffffu, bf, off);
        if (ov < bv || (ov == bv && oi < bf)) { bv = ov; bf = oi; }
    }
    if ((t & 31) == 0) { wv[t >> 5] = bv; wi[t >> 5] = bf; }
    __syncthreads();

    if (t == 0) {
        float mv = wv[0]; int mi = wi[0];
#pragma unroll
        for (int w = 1; w < TPB / 32; ++w) {
            float ov = wv[w]; int oi = wi[w];
            if (ov < mv || (ov == mv && oi < mi)) { mv = ov; mi = oi; }
        }
        int i1 = mi >> 8;
        int i2 = mi & 255;
        float4 a = s1[i1];
        float4 A = sA[i2 >> 1];
        float4 B = sB[i2 >> 1];
        int odd = i2 & 1;
        float bx = odd ? A.y : A.x;
        float by = odd ? A.w : A.z;
        float bz = odd ? B.y : B.x;

        float dx = __fsub_rn(a.x, bx);
        float dy = __fsub_rn(a.y, by);
        float dz = __fsub_rn(a.z, bz);
        float lend = __fsqrt_rn(__fadd_rn(__fadd_rn(__fmul_rn(dx, dx),
                                                    __fmul_rn(dz, dz)),
                                          __fmul_rn(dy, dy)));
        float denom = (lend > 0.0f) ? lend : 1.0f;
        float ux = __fdiv_rn(dx, denom);
        float uy = __fdiv_rn(dy, denom);
        float uz = __fdiv_rn(dz, denom);

        float* o = out + (size_t)e * 19;
        o[0]  = a.x; o[1]  = a.y; o[2]  = a.z;   // v1
        o[3]  = bx;  o[4]  = by;  o[5]  = bz;    // v2
        o[6]  = ux;  o[7]  = uy;  o[8]  = uz;    // disp
        o[9]  = lend;
        o[10] = __fmul_rn(ux, ux); o[11] = __fmul_rn(ux, uy); o[12] = __fmul_rn(ux, uz);
        o[13] = __fmul_rn(uy, ux); o[14] = __fmul_rn(uy, uy); o[15] = __fmul_rn(uy, uz);
        o[16] = __fmul_rn(uz, ux); o[17] = __fmul_rn(uz, uy); o[18] = __fmul_rn(uz, uz);
    }
}

extern "C" void kernel_launch(void* const* d_in, const int* in_sizes, int n_in,
                              void* d_out, int out_size)
{
    const float* data   = (const float*)d_in[0];   // [N_VOX, 5] f32
    const int*   clusts = (const int*)  d_in[1];   // [N_CLUST, 256] i32
    const int*   ei     = (const int*)  d_in[2];   // [2, E] i32
    float*       out    = (float*)d_out;           // [E, 19] f32

    int n_edge = in_sizes[2] / 2;
    clust_geo_edge_kernel<<<n_edge, TPB>>>(data, clusts, ei, out, n_edge);
}

// round 10
// speedup vs baseline: 1.4818x; 1.4818x over previous
#include <cuda_runtime.h>
#include <cstdint>

#define KC  256      // CLUST_SIZE
#define TPB 128      // threads per CTA; each thread owns rows 2t and 2t+1

typedef unsigned long long u64;

// ---- packed f32x2 ops (Blackwell). Lane rounding == scalar .rn rounding,
// ---- so results are bitwise identical to the scalar reference chain. ----
__device__ __forceinline__ u64 mul2(u64 a, u64 b) {
    u64 r; asm("mul.rn.f32x2 %0, %1, %2;" : "=l"(r) : "l"(a), "l"(b)); return r;
}
__device__ __forceinline__ u64 add2(u64 a, u64 b) {
    u64 r; asm("add.rn.f32x2 %0, %1, %2;" : "=l"(r) : "l"(a), "l"(b)); return r;
}
__device__ __forceinline__ u64 fma2p(u64 a, u64 b, u64 c) {
    u64 r; asm("fma.rn.f32x2 %0, %1, %2, %3;" : "=l"(r) : "l"(a), "l"(b), "l"(c)); return r;
}
__device__ __forceinline__ u64 pk2(float lo, float hi) {
    union { float2 f; u64 u; } c; c.f = make_float2(lo, hi); return c.u;
}
__device__ __forceinline__ float2 f2(u64 v) {
    union { u64 u; float2 f; } c; c.u = v; return c.f;
}

// min-blocks 9 => <=56 regs (9*128*56 = 64512 <= 64K) => 36 warps/SM theo.
// A 5-reg shave from the natural 61 should rematerialize, not spill.
__global__ __launch_bounds__(TPB, 9)
void clust_geo_edge_kernel(const float* __restrict__ data,     // [N_VOX, 5]
                           const int*   __restrict__ clusts,   // [N_CLUST, 256]
                           const int*   __restrict__ ei,       // [2, E]
                           float*       __restrict__ out,      // [E, 19]
                           int n_edge)
{
    __shared__ float4 s1[KC];        // cluster-1 rows: {x, y, z, h=0.5*n}
    // cluster-2 j-pairs, byte layout == packed u64 pairs:
    //   sA[p] = {x0,x1,y0,y1} -> ulonglong2 { (x0,x1), (y0,y1) }
    //   sB[p] = {z0,z1,h0,h1} -> ulonglong2 { (z0,z1), (h0,h1) }
    __shared__ float4 sA[KC / 2];
    __shared__ float4 sB[KC / 2];
    __shared__ float  wv[TPB / 32];
    __shared__ int    wi[TPB / 32];

    const int e = blockIdx.x;
    const int t = threadIdx.x;
    const int c1 = ei[e];
    const int c2 = ei[n_edge + e];

    // ---- gather; arithmetic bit-identical to the passing rounds:
    //      n via pair02 tree rn(rn(x^2+z^2)+y^2), h = 0.5*n (exact) ----
    float4 r0, r1;
    {
        int2 va = reinterpret_cast<const int2*>(clusts + c1 * KC)[t];
        const float* pa = data + (size_t)va.x * 5;
        const float* pb = data + (size_t)va.y * 5;
        float x = pa[0], y = pa[1], z = pa[2];
        float h = 0.5f * __fadd_rn(__fadd_rn(__fmul_rn(x, x), __fmul_rn(z, z)),
                                   __fmul_rn(y, y));
        r0 = make_float4(x, y, z, h);
        s1[2 * t] = r0;
        x = pb[0]; y = pb[1]; z = pb[2];
        h = 0.5f * __fadd_rn(__fadd_rn(__fmul_rn(x, x), __fmul_rn(z, z)),
                             __fmul_rn(y, y));
        r1 = make_float4(x, y, z, h);
        s1[2 * t + 1] = r1;

        int2 vb = reinterpret_cast<const int2*>(clusts + c2 * KC)[t];
        const float* qa = data + (size_t)vb.x * 5;
        const float* qb = data + (size_t)vb.y * 5;
        float X0 = qa[0], Y0 = qa[1], Z0 = qa[2];
        float H0 = 0.5f * __fadd_rn(__fadd_rn(__fmul_rn(X0, X0), __fmul_rn(Z0, Z0)),
                                    __fmul_rn(Y0, Y0));
        float X1 = qb[0], Y1 = qb[1], Z1 = qb[2];
        float H1 = 0.5f * __fadd_rn(__fadd_rn(__fmul_rn(X1, X1), __fmul_rn(Z1, Z1)),
                                    __fmul_rn(Y1, Y1));
        sA[t] = make_float4(X0, X1, Y0, Y1);
        sB[t] = make_float4(Z0, Z1, H0, H1);
    }
    __syncthreads();

    // Row constants, negated so the fma chain yields -c exactly
    // ( rn(-x) == -rn(x);  d = (h1+h2) + (-c)  is bitwise  (h1+h2) - c ).
    const u64 nx0 = pk2(-r0.x, -r0.x), ny0 = pk2(-r0.y, -r0.y),
              nz0 = pk2(-r0.z, -r0.z), hh0 = pk2( r0.w,  r0.w);
    const u64 nx1 = pk2(-r1.x, -r1.x), ny1 = pk2(-r1.y, -r1.y),
              nz1 = pk2(-r1.z, -r1.z), hh1 = pk2( r1.w,  r1.w);

    const ulonglong2* qAB = reinterpret_cast<const ulonglong2*>(sA);
    const ulonglong2* qZH = reinterpret_cast<const ulonglong2*>(sB);

    const float INF = __int_as_float(0x7f800000);
    float best0 = INF, best1 = INF;
    int   bj0 = 0,     bj1 = 0;

#pragma unroll 2
    for (int kb = 0; kb < KC / 8; ++kb) {           // 8 j per block = 4 packed pairs
        ulonglong2 ab0 = qAB[kb * 4 + 0], zh0 = qZH[kb * 4 + 0];
        ulonglong2 ab1 = qAB[kb * 4 + 1], zh1 = qZH[kb * 4 + 1];
        ulonglong2 ab2 = qAB[kb * 4 + 2], zh2 = qZH[kb * 4 + 2];
        ulonglong2 ab3 = qAB[kb * 4 + 3], zh3 = qZH[kb * 4 + 3];

        // ---------------- row 0 ----------------
        {
            u64 d0 = add2(add2(hh0, zh0.y), fma2p(nz0, zh0.x, fma2p(ny0, ab0.y, mul2(nx0, ab0.x))));
            u64 d1 = add2(add2(hh0, zh1.y), fma2p(nz0, zh1.x, fma2p(ny0, ab1.y, mul2(nx0, ab1.x))));
            u64 d2 = add2(add2(hh0, zh2.y), fma2p(nz0, zh2.x, fma2p(ny0, ab2.y, mul2(nx0, ab2.x))));
            u64 d3 = add2(add2(hh0, zh3.y), fma2p(nz0, zh3.x, fma2p(ny0, ab3.y, mul2(nx0, ab3.x))));
            float2 a = f2(d0), b = f2(d1), c = f2(d2), d = f2(d3);
            float bm = fminf(fminf(fminf(a.x, a.y), fminf(b.x, b.y)),
                             fminf(fminf(c.x, c.y), fminf(d.x, d.y)));
            if (bm < best0) {                       // strict <: earlier block wins ties
                best0 = bm;
                int jb = kb * 8;                    // descending overwrite -> lowest j wins
                if (d.y == bm) bj0 = jb + 7;
                if (d.x == bm) bj0 = jb + 6;
                if (c.y == bm) bj0 = jb + 5;
                if (c.x == bm) bj0 = jb + 4;
                if (b.y == bm) bj0 = jb + 3;
                if (b.x == bm) bj0 = jb + 2;
                if (a.y == bm) bj0 = jb + 1;
                if (a.x == bm) bj0 = jb + 0;
            }
        }
        // ---------------- row 1 ----------------
        {
            u64 d0 = add2(add2(hh1, zh0.y), fma2p(nz1, zh0.x, fma2p(ny1, ab0.y, mul2(nx1, ab0.x))));
            u64 d1 = add2(add2(hh1, zh1.y), fma2p(nz1, zh1.x, fma2p(ny1, ab1.y, mul2(nx1, ab1.x))));
            u64 d2 = add2(add2(hh1, zh2.y), fma2p(nz1, zh2.x, fma2p(ny1, ab2.y, mul2(nx1, ab2.x))));
            u64 d3 = add2(add2(hh1, zh3.y), fma2p(nz1, zh3.x, fma2p(ny1, ab3.y, mul2(nx1, ab3.x))));
            float2 a = f2(d0), b = f2(d1), c = f2(d2), d = f2(d3);
            float bm = fminf(fminf(fminf(a.x, a.y), fminf(b.x, b.y)),
                             fminf(fminf(c.x, c.y), fminf(d.x, d.y)));
            if (bm < best1) {
                best1 = bm;
                int jb = kb * 8;
                if (d.y == bm) bj1 = jb + 7;
                if (d.x == bm) bj1 = jb + 6;
                if (c.y == bm) bj1 = jb + 5;
                if (c.x == bm) bj1 = jb + 4;
                if (b.y == bm) bj1 = jb + 3;
                if (b.x == bm) bj1 = jb + 2;
                if (a.y == bm) bj1 = jb + 1;
                if (a.x == bm) bj1 = jb + 0;
            }
        }
    }

    // Merge the two rows. Row 2t's flat indices are all smaller than row
    // 2t+1's, so strict < keeps first-occurrence semantics exactly.
    float bv;  int bf;
    if (best1 < best0) { bv = best1; bf = ((2 * t + 1) << 8) | bj1; }
    else               { bv = best0; bf = ((2 * t)     << 8) | bj0; }

    // Warp shuffle reduction, lexicographic (value, flat index) — no barriers.
#pragma unroll
    for (int off = 16; off > 0; off >>= 1) {
        float ov = __shfl_down_sync(0xffffffffu, bv, off);
        int   oi = __shfl_down_sync(0xffffffffu, bf, off);
        if (ov < bv || (ov == bv && oi < bf)) { bv = ov; bf = oi; }
    }
    if ((t & 31) == 0) { wv[t >> 5] = bv; wi[t >> 5] = bf; }
    __syncthreads();

    if (t == 0) {
        float mv = wv[0]; int mi = wi[0];
#pragma unroll
        for (int w = 1; w < TPB / 32; ++w) {
            float ov = wv[w]; int oi = wi[w];
            if (ov < mv || (ov == mv && oi < mi)) { mv = ov; mi = oi; }
        }
        int i1 = mi >> 8;
        int i2 = mi & 255;
        float4 a = s1[i1];
        float4 A = sA[i2 >> 1];
        float4 B = sB[i2 >> 1];
        int odd = i2 & 1;
        float bx = odd ? A.y : A.x;
        float by = odd ? A.w : A.z;
        float bz = odd ? B.y : B.x;

        float dx = __fsub_rn(a.x, bx);
        float dy = __fsub_rn(a.y, by);
        float dz = __fsub_rn(a.z, bz);
        float lend = __fsqrt_rn(__fadd_rn(__fadd_rn(__fmul_rn(dx, dx),
                                                    __fmul_rn(dz, dz)),
                                          __fmul_rn(dy, dy)));
        float denom = (lend > 0.0f) ? lend : 1.0f;
        float ux = __fdiv_rn(dx, denom);
        float uy = __fdiv_rn(dy, denom);
        float uz = __fdiv_rn(dz, denom);

        float* o = out + (size_t)e * 19;
        o[0]  = a.x; o[1]  = a.y; o[2]  = a.z;   // v1
        o[3]  = bx;  o[4]  = by;  o[5]  = bz;    // v2
        o[6]  = ux;  o[7]  = uy;  o[8]  = uz;    // disp
        o[9]  = lend;
        o[10] = __fmul_rn(ux, ux); o[11] = __fmul_rn(ux, uy); o[12] = __fmul_rn(ux, uz);
        o[13] = __fmul_rn(uy, ux); o[14] = __fmul_rn(uy, uy); o[15] = __fmul_rn(uy, uz);
        o[16] = __fmul_rn(uz, ux); o[17] = __fmul_rn(uz, uy); o[18] = __fmul_rn(uz, uz);
    }
}

extern "C" void kernel_launch(void* const* d_in, const int* in_sizes, int n_in,
                              void* d_out, int out_size)
{
    const float* data   = (const float*)d_in[0];   // [N_VOX, 5] f32
    const int*   clusts = (const int*)  d_in[1];   // [N_CLUST, 256] i32
    const int*   ei     = (const int*)  d_in[2];   // [2, E] i32
    float*       out    = (float*)d_out;           // [E, 19] f32

    int n_edge = in_sizes[2] / 2;
    clust_geo_edge_kernel<<<n_edge, TPB>>>(data, clusts, ei, out, n_edge);
}

// round 11
// speedup vs baseline: 1.7020x; 1.1486x over previous
#include <cuda_runtime.h>
#include <cstdint>

#define KC  256      // CLUST_SIZE
#define TPB 128      // threads per CTA; each thread owns rows 2t and 2t+1

typedef unsigned long long u64;

__device__ __forceinline__ u64 pk2(float lo, float hi) {
    union { float2 f; u64 u; } c; c.f = make_float2(lo, hi); return c.u;
}

// Fused packed distance: d = rn( rn(h1+h2) + (-c) ),
//   -c = fma(nz,qz, fma(ny,qy, mul(nx,qx)))   (nx,ny,nz pre-negated).
// Identical op sequence/rounding to the frozen passing arithmetic; the final
// mov.b64 {lo,hi} is a register pair-split ptxas eliminates.
__device__ __forceinline__ void dcalc(u64 nx, u64 ny, u64 nz, u64 hh,
                                      u64 qx, u64 qy, u64 qz, u64 qh,
                                      float& lo, float& hi)
{
    asm("{\n\t"
        ".reg .b64 c, s;\n\t"
        "mul.rn.f32x2 c, %2, %3;\n\t"
        "fma.rn.f32x2 c, %4, %5, c;\n\t"
        "fma.rn.f32x2 c, %6, %7, c;\n\t"
        "add.rn.f32x2 s, %8, %9;\n\t"
        "add.rn.f32x2 s, s, c;\n\t"
        "mov.b64 {%0, %1}, s;\n\t"
        "}"
        : "=f"(lo), "=f"(hi)
        : "l"(nx), "l"(qx), "l"(ny), "l"(qy),
          "l"(nz), "l"(qz), "l"(hh), "l"(qh));
}

__global__ __launch_bounds__(TPB)
void clust_geo_edge_kernel(const float* __restrict__ data,     // [N_VOX, 5]
                           const int*   __restrict__ clusts,   // [N_CLUST, 256]
                           const int*   __restrict__ ei,       // [2, E]
                           float*       __restrict__ out,      // [E, 19]
                           int n_edge)
{
    __shared__ float4 s1[KC];        // cluster-1 rows: {x, y, z, h=0.5*n}
    // cluster-2, interleaved pair tiles. For j-pair p (j = 2p, 2p+1):
    //   sT[(p>>2)*8 + (p&3)*2 + 0] = {x0,x1,y0,y1}   (AB)
    //   sT[(p>>2)*8 + (p&3)*2 + 1] = {z0,z1,h0,h1}   (ZH)
    // => one 8-j block = 128 contiguous bytes, single base pointer + imm.
    __shared__ float4 sT[KC];        // 128 pairs * 2 float4
    __shared__ float  wv[TPB / 32];
    __shared__ int    wi[TPB / 32];

    const int e = blockIdx.x;
    const int t = threadIdx.x;
    const int c1 = ei[e];
    const int c2 = ei[n_edge + e];

    // ---- gather; arithmetic bit-identical to the passing rounds:
    //      n via pair02 tree rn(rn(x^2+z^2)+y^2), h = 0.5*n (exact) ----
    float4 r0, r1;
    {
        int2 va = reinterpret_cast<const int2*>(clusts + c1 * KC)[t];
        const float* pa = data + (size_t)va.x * 5;
        const float* pb = data + (size_t)va.y * 5;
        float x = pa[0], y = pa[1], z = pa[2];
        float h = 0.5f * __fadd_rn(__fadd_rn(__fmul_rn(x, x), __fmul_rn(z, z)),
                                   __fmul_rn(y, y));
        r0 = make_float4(x, y, z, h);
        s1[2 * t] = r0;
        x = pb[0]; y = pb[1]; z = pb[2];
        h = 0.5f * __fadd_rn(__fadd_rn(__fmul_rn(x, x), __fmul_rn(z, z)),
                             __fmul_rn(y, y));
        r1 = make_float4(x, y, z, h);
        s1[2 * t + 1] = r1;

        int2 vb = reinterpret_cast<const int2*>(clusts + c2 * KC)[t];
        const float* qa = data + (size_t)vb.x * 5;
        const float* qb = data + (size_t)vb.y * 5;
        float X0 = qa[0], Y0 = qa[1], Z0 = qa[2];
        float H0 = 0.5f * __fadd_rn(__fadd_rn(__fmul_rn(X0, X0), __fmul_rn(Z0, Z0)),
                                    __fmul_rn(Y0, Y0));
        float X1 = qb[0], Y1 = qb[1], Z1 = qb[2];
        float H1 = 0.5f * __fadd_rn(__fadd_rn(__fmul_rn(X1, X1), __fmul_rn(Z1, Z1)),
                                    __fmul_rn(Y1, Y1));
        int base = (t >> 2) * 8 + (t & 3) * 2;     // pair p = t
        sT[base + 0] = make_float4(X0, X1, Y0, Y1);
        sT[base + 1] = make_float4(Z0, Z1, H0, H1);
    }
    __syncthreads();

    // Row constants, negated so the fma chain yields -c exactly (rn(-x)=-rn(x)).
    const u64 nx0 = pk2(-r0.x, -r0.x), ny0 = pk2(-r0.y, -r0.y),
              nz0 = pk2(-r0.z, -r0.z), hh0 = pk2( r0.w,  r0.w);
    const u64 nx1 = pk2(-r1.x, -r1.x), ny1 = pk2(-r1.y, -r1.y),
              nz1 = pk2(-r1.z, -r1.z), hh1 = pk2( r1.w,  r1.w);

    const float INF = __int_as_float(0x7f800000);
    float best0 = INF, best1 = INF;
    int   bj0 = 0,     bj1 = 0;

    const ulonglong2* pt = reinterpret_cast<const ulonglong2*>(sT);

#pragma unroll 2
    for (int kb = 0; kb < KC / 8; ++kb) {          // 8 j per block = 128 bytes
        ulonglong2 ab0 = pt[0], zh0 = pt[1];
        ulonglong2 ab1 = pt[2], zh1 = pt[3];
        ulonglong2 ab2 = pt[4], zh2 = pt[5];
        ulonglong2 ab3 = pt[6], zh3 = pt[7];
        pt += 8;

        // ---------------- row 0 ----------------
        {
            float a0, a1, b0, b1, c0, c1, e0, e1;
            dcalc(nx0, ny0, nz0, hh0, ab0.x, ab0.y, zh0.x, zh0.y, a0, a1);
            dcalc(nx0, ny0, nz0, hh0, ab1.x, ab1.y, zh1.x, zh1.y, b0, b1);
            dcalc(nx0, ny0, nz0, hh0, ab2.x, ab2.y, zh2.x, zh2.y, c0, c1);
            dcalc(nx0, ny0, nz0, hh0, ab3.x, ab3.y, zh3.x, zh3.y, e0, e1);
            float bm = fminf(fminf(fminf(a0, a1), fminf(b0, b1)),
                             fminf(fminf(c0, c1), fminf(e0, e1)));
            if (bm < best0) {                      // strict <: earlier block wins ties
                best0 = bm;
                int jb = kb * 8;                   // descending overwrite -> lowest j
                if (e1 == bm) bj0 = jb + 7;
                if (e0 == bm) bj0 = jb + 6;
                if (c1 == bm) bj0 = jb + 5;
                if (c0 == bm) bj0 = jb + 4;
                if (b1 == bm) bj0 = jb + 3;
                if (b0 == bm) bj0 = jb + 2;
                if (a1 == bm) bj0 = jb + 1;
                if (a0 == bm) bj0 = jb + 0;
            }
        }
        // ---------------- row 1 ----------------
        {
            float a0, a1, b0, b1, c0, c1, e0, e1;
            dcalc(nx1, ny1, nz1, hh1, ab0.x, ab0.y, zh0.x, zh0.y, a0, a1);
            dcalc(nx1, ny1, nz1, hh1, ab1.x, ab1.y, zh1.x, zh1.y, b0, b1);
            dcalc(nx1, ny1, nz1, hh1, ab2.x, ab2.y, zh2.x, zh2.y, c0, c1);
            dcalc(nx1, ny1, nz1, hh1, ab3.x, ab3.y, zh3.x, zh3.y, e0, e1);
            float bm = fminf(fminf(fminf(a0, a1), fminf(b0, b1)),
                             fminf(fminf(c0, c1), fminf(e0, e1)));
            if (bm < best1) {
                best1 = bm;
                int jb = kb * 8;
                if (e1 == bm) bj1 = jb + 7;
                if (e0 == bm) bj1 = jb + 6;
                if (c1 == bm) bj1 = jb + 5;
                if (c0 == bm) bj1 = jb + 4;
                if (b1 == bm) bj1 = jb + 3;
                if (b0 == bm) bj1 = jb + 2;
                if (a1 == bm) bj1 = jb + 1;
                if (a0 == bm) bj1 = jb + 0;
            }
        }
    }

    // Merge the two rows. Row 2t's flat indices are all smaller than row
    // 2t+1's, so strict < keeps first-occurrence semantics exactly.
    float bv;  int bf;
    if (best1 < best0) { bv = best1; bf = ((2 * t + 1) << 8) | bj1; }
    else               { bv = best0; bf = ((2 * t)     << 8) | bj0; }

    // Warp shuffle reduction, lexicographic (value, flat index) — no barriers.
#pragma unroll
    for (int off = 16; off > 0; off >>= 1) {
        float ov = __shfl_down_sync(0xffffffffu, bv, off);
        int   oi = __shfl_down_sync(0xffffffffu, bf, off);
        if (ov < bv || (ov == bv && oi < bf)) { bv = ov; bf = oi; }
    }
    if ((t & 31) == 0) { wv[t >> 5] = bv; wi[t >> 5] = bf; }
    __syncthreads();

    if (t == 0) {
        float mv = wv[0]; int mi = wi[0];
#pragma unroll
        for (int w = 1; w < TPB / 32; ++w) {
            float ov = wv[w]; int oi = wi[w];
            if (ov < mv || (ov == mv && oi < mi)) { mv = ov; mi = oi; }
        }
        int i1 = mi >> 8;
        int i2 = mi & 255;
        float4 a = s1[i1];
        int p = i2 >> 1, odd = i2 & 1;
        int base = (p >> 2) * 8 + (p & 3) * 2;
        float4 A = sT[base + 0];
        float4 B = sT[base + 1];
        float bx = odd ? A.y : A.x;
        float by = odd ? A.w : A.z;
        float bz = odd ? B.y : B.x;

        float dx = __fsub_rn(a.x, bx);
        float dy = __fsub_rn(a.y, by);
        float dz = __fsub_rn(a.z, bz);
        float lend = __fsqrt_rn(__fadd_rn(__fadd_rn(__fmul_rn(dx, dx),
                                                    __fmul_rn(dz, dz)),
                                          __fmul_rn(dy, dy)));
        float denom = (lend > 0.0f) ? lend : 1.0f;
        float ux = __fdiv_rn(dx, denom);
        float uy = __fdiv_rn(dy, denom);
        float uz = __fdiv_rn(dz, denom);

        float* o = out + (size_t)e * 19;
        o[0]  = a.x; o[1]  = a.y; o[2]  = a.z;   // v1
        o[3]  = bx;  o[4]  = by;  o[5]  = bz;    // v2
        o[6]  = ux;  o[7]  = uy;  o[8]  = uz;    // disp
        o[9]  = lend;
        o[10] = __fmul_rn(ux, ux); o[11] = __fmul_rn(ux, uy); o[12] = __fmul_rn(ux, uz);
        o[13] = __fmul_rn(uy, ux); o[14] = __fmul_rn(uy, uy); o[15] = __fmul_rn(uy, uz);
        o[16] = __fmul_rn(uz, ux); o[17] = __fmul_rn(uz, uy); o[18] = __fmul_rn(uz, uz);
    }
}

extern "C" void kernel_launch(void* const* d_in, const int* in_sizes, int n_in,
                              void* d_out, int out_size)
{
    const float* data   = (const float*)d_in[0];   // [N_VOX, 5] f32
    const int*   clusts = (const int*)  d_in[1];   // [N_CLUST, 256] i32
    const int*   ei     = (const int*)  d_in[2];   // [2, E] i32
    float*       out    = (float*)d_out;           // [E, 19] f32

    int n_edge = in_sizes[2] / 2;
    clust_geo_edge_kernel<<<n_edge, TPB>>>(data, clusts, ei, out, n_edge);
}